// round 16
// baseline (speedup 1.0000x reference)
#include <cuda_runtime.h>
#include <cuda_fp16.h>
#include <cstdint>
#include <math.h>

#define BB 32
#define SS 64
#define CC 256
#define N2 4096

#define ROWB 528                      // fp32 stage row stride (bytes) per channel
#define STAGE_BYTES (32 * ROWB)       // 16896
#define N_SLOT 4
#define DSM_BYTES (N_SLOT * STAGE_BYTES)   // 67584

__device__ int      g_topk[SS];
__device__ int      g_vstart[BB + 1];
__device__ float    g_negsum[SS];
__device__ float    g_all[SS * SS];
__device__ uint4    g_Afr[16 * 4 * 32];   // A fragments [ks][mt][lane]
__device__ unsigned g_done;

__device__ __forceinline__ uint32_t smem_u32(const void* p) {
    uint32_t a;
    asm("{ .reg .u64 t; cvta.to.shared.u64 t, %1; cvt.u32.u64 %0, t; }" : "=r"(a) : "l"(p));
    return a;
}
#define CP16(dst, src) \
    asm volatile("cp.async.cg.shared.global [%0], [%1], 16;" :: "r"(dst), "l"(src))
#define CP_COMMIT() asm volatile("cp.async.commit_group;")
#define CP_WAIT2()  asm volatile("cp.async.wait_group 2;")

#define MMAF16(d, a0, a1, a2, a3, b0, b1) \
    asm volatile("mma.sync.aligned.m16n8k16.row.col.f32.f16.f16.f32 " \
                 "{%0,%1,%2,%3}, {%4,%5,%6,%7}, {%8,%9}, {%0,%1,%2,%3};" \
                 : "+f"((d)[0]), "+f"((d)[1]), "+f"((d)[2]), "+f"((d)[3]) \
                 : "r"(a0), "r"(a1), "r"(a2), "r"(a3), "r"(b0), "r"(b1))

// ---------------------------------------------------------------------------
// k_prep: bid<64 = sentence s: normalize -> fragment-order A; iou argmax.
//         bid==64: vstart prefix + negsum + g_done init.
__global__ void k_prep(const float* __restrict__ sents, const float* __restrict__ iou,
                       const int* __restrict__ ntgt) {
    int bid = blockIdx.x, tid = threadIdx.x;
    if (bid == 64) {
        if (tid < SS) g_negsum[tid] = 0.f;
        if (tid == 0) {
            g_done = 0u;
            int acc = 0;
            g_vstart[0] = 0;
            for (int b = 0; b < BB; b++) {
                acc += ntgt[b];
                if (acc > SS) acc = SS;
                g_vstart[b + 1] = acc;
            }
        }
        return;
    }
    int s = bid;
    int lane = tid & 31, w = tid >> 5;
    __shared__ float wsum[8];
    __shared__ float amax[8];
    __shared__ int   aidx[8];

    float x = sents[s * CC + tid];
    float q = x * x;
#pragma unroll
    for (int o = 16; o; o >>= 1) q += __shfl_xor_sync(~0u, q, o);
    if (lane == 0) wsum[w] = q;
    __syncthreads();
    float tot = wsum[0] + wsum[1] + wsum[2] + wsum[3] +
                wsum[4] + wsum[5] + wsum[6] + wsum[7];
    float inv = 1.f / fmaxf(sqrtf(tot), 1e-12f);
    __half h = __float2half_rn(x * inv);
    int c = tid;
    int u4 = ((c >> 4) * 4 + (s >> 4)) * 32 + (s & 7) * 4 + ((c & 7) >> 1);
    int byte = u4 * 16 + ((s >> 3) & 1) * 4 + ((c >> 3) & 1) * 8 + (c & 1) * 2;
    *(__half*)((char*)g_Afr + byte) = h;

    float best = -1.f;
    int bi = 0;
    const float* irow = iou + (size_t)s * N2;
#pragma unroll
    for (int k = 0; k < 16; k++) {
        int ij = tid + 256 * k;
        if ((ij & 63) >= (ij >> 6)) {
            float v = irow[ij];
            if (v > best) { best = v; bi = ij; }
        }
    }
#pragma unroll
    for (int o = 16; o; o >>= 1) {
        float ov = __shfl_xor_sync(~0u, best, o);
        int   oi = __shfl_xor_sync(~0u, bi, o);
        if (ov > best || (ov == best && oi < bi)) { best = ov; bi = oi; }
    }
    if (lane == 0) { amax[w] = best; aidx[w] = bi; }
    __syncthreads();
    if (tid == 0) {
        float bb = amax[0]; int ii = aidx[0];
        for (int k = 1; k < 8; k++)
            if (amax[k] > bb || (amax[k] == bb && aidx[k] < ii)) { bb = amax[k]; ii = aidx[k]; }
        g_topk[s] = ii;
    }
}

// ---------------------------------------------------------------------------
// k_main: CTA (t,b). 4-slot cp.async fp32 ring (2-ahead), ONE barrier/stage,
// warp-owned 16-prop strips: direct LDS fp32 -> in-register fp16 -> HMMA.
__global__ void __launch_bounds__(256, 3) k_main(const float* __restrict__ video,
                                                 const float* __restrict__ iou,
                                                 float* __restrict__ out) {
    extern __shared__ __align__(16) char dsm[];
    __shared__ float sneg[SS];
    __shared__ float red[128];
    __shared__ int   flag;

    int tid = threadIdx.x;
    int lane = tid & 31, w = tid >> 5;
    int t = blockIdx.x, b = blockIdx.y;
    int ij0 = t * 128, i0 = 2 * t;
    int f0 = i0 >> 3, f1 = (i0 + 1) >> 3;
    int pstart0 = f0 * 8, pstart1 = 64 + f1 * 8;
    int seg0u = 16 - 2 * f0;
    int upr = 32 - 2 * (f0 + f1);

    // loader mapping: 8 threads per channel row (32 ch per stage)
    int lch = tid >> 3, lj = tid & 7;
    const float* gch = video + (size_t)b * CC * N2 + ij0 + (size_t)lch * N2;
    uint32_t srow = smem_u32(dsm) + lch * ROWB;

    // prologue: stages 0,1 into slots 0,1
#pragma unroll
    for (int st = 0; st < 2; st++) {
        const float* gs = gch + (size_t)(st * 32) * N2;
#pragma unroll
        for (int u4 = 0; u4 < 4; u4++) {
            int u = lj + u4 * 8;
            if (u < upr) {
                int prop = (u < seg0u) ? (pstart0 + 4 * u) : (pstart1 + 4 * (u - seg0u));
                CP16(srow + st * STAGE_BYTES + prop * 4, gs + prop);
            }
        }
        CP_COMMIT();
    }

    if (tid < SS) sneg[tid] = 0.f;

    // warp strip: h = row (i0 or i0+1), jq = 16-col block
    int h = w >> 2, jq = w & 3;
    int i = i0 + h;
    int j0 = jq * 16;
    int ptile0 = h * 64 + j0;                 // strip base within 128-prop tile
    bool wact = (j0 + 15 >= i);               // strip has any valid proposal

    int q = lane & 3, nl = lane >> 2;
    const char* cbase = dsm + (ptile0 + nl) * 4;   // + slot + ch*ROWB at use
    const uint4* Afr = g_Afr + lane;

    float acc[32];
#pragma unroll
    for (int k = 0; k < 32; k++) acc[k] = 0.f;
    float ss0 = 0.f, ss1 = 0.f;

    for (int st = 0; st < 8; st++) {
        // issue stage st+2 into slot (st+2)&3 (safe: consume(st-2) ordered by
        // barrier(st-1) before any thread reaches this point)
        if (st + 2 < 8) {
            const float* gs = gch + (size_t)((st + 2) * 32) * N2;
            uint32_t sd = srow + ((st + 2) & 3) * STAGE_BYTES;
#pragma unroll
            for (int u4 = 0; u4 < 4; u4++) {
                int u = lj + u4 * 8;
                if (u < upr) {
                    int prop = (u < seg0u) ? (pstart0 + 4 * u) : (pstart1 + 4 * (u - seg0u));
                    CP16(sd + prop * 4, gs + prop);
                }
            }
        }
        CP_COMMIT();
        CP_WAIT2();
        __syncthreads();   // stage st globally visible; slot (st+2)&3 free

        if (wact) {
            const char* slot = cbase + (st & 3) * STAGE_BYTES;
#pragma unroll
            for (int kk = 0; kk < 2; kk++) {
                const char* p0 = slot + (size_t)(kk * 16 + 2 * q) * ROWB;
                float x0 = *(const float*)(p0);
                float x1 = *(const float*)(p0 + ROWB);
                float x2 = *(const float*)(p0 + 8 * ROWB);
                float x3 = *(const float*)(p0 + 9 * ROWB);
                float y0 = *(const float*)(p0 + 32);
                float y1 = *(const float*)(p0 + ROWB + 32);
                float y2 = *(const float*)(p0 + 8 * ROWB + 32);
                float y3 = *(const float*)(p0 + 9 * ROWB + 32);
                ss0 += x0 * x0 + x1 * x1 + x2 * x2 + x3 * x3;
                ss1 += y0 * y0 + y1 * y1 + y2 * y2 + y3 * y3;
                __half2 h00 = __floats2half2_rn(x0, x1);
                __half2 h01 = __floats2half2_rn(x2, x3);
                __half2 h10 = __floats2half2_rn(y0, y1);
                __half2 h11 = __floats2half2_rn(y2, y3);
                uint32_t b00 = *(uint32_t*)&h00, b01 = *(uint32_t*)&h01;
                uint32_t b10 = *(uint32_t*)&h10, b11 = *(uint32_t*)&h11;
#pragma unroll
                for (int mt = 0; mt < 4; mt++) {
                    uint4 a = Afr[((st * 2 + kk) * 4 + mt) * 32];
                    MMAF16(acc + mt * 8,     a.x, a.y, a.z, a.w, b00, b01);
                    MMAF16(acc + mt * 8 + 4, a.x, a.y, a.z, a.w, b10, b11);
                }
            }
        }
    }

    if (wact) {
        // per-prop inverse norms (quad covers all channels of props nl / nl+8)
        ss0 += __shfl_xor_sync(~0u, ss0, 1); ss0 += __shfl_xor_sync(~0u, ss0, 2);
        ss1 += __shfl_xor_sync(~0u, ss1, 1); ss1 += __shfl_xor_sync(~0u, ss1, 2);
        float inv0 = rsqrtf(fmaxf(ss0, 1e-24f));
        float inv1 = rsqrtf(fmaxf(ss1, 1e-24f));
        float invc[4];
        invc[0] = __shfl_sync(~0u, inv0, 8 * q);
        invc[1] = __shfl_sync(~0u, inv0, 8 * q + 4);
        invc[2] = __shfl_sync(~0u, inv1, 8 * q);
        invc[3] = __shfl_sync(~0u, inv1, 8 * q + 4);

        int jc[4];
        jc[0] = j0 + 2 * q;     jc[1] = jc[0] + 1;
        jc[2] = j0 + 8 + 2 * q; jc[3] = jc[2] + 1;
        bool vj[4];
#pragma unroll
        for (int e = 0; e < 4; e++) vj[e] = (jc[e] >= i);

        int vs0 = g_vstart[b], vs1 = g_vstart[b + 1];
        int nc = 0, capC[4], capS4[4];
        for (int cs = vs0; cs < vs1; cs++) {
            int rel = g_topk[cs] - i * 64 - j0;
            if (rel >= 0 && rel < 16 && nc < 4) { capC[nc] = j0 + rel; capS4[nc] = cs; nc++; }
        }

        float rsum[8];
#pragma unroll
        for (int mt = 0; mt < 4; mt++) {
            int sA = mt * 16 + nl, sB = sA + 8;
            bool hA = (sA >= vs0 && sA < vs1);
            bool hB = (sB >= vs0 && sB < vs1);
            float rA = 0.f, rB = 0.f;
#pragma unroll
            for (int e = 0; e < 4; e++) {
                int blk = e >> 1, par = e & 1;
                float scA = acc[mt * 8 + blk * 4 + par] * invc[e];
                float scB = acc[mt * 8 + blk * 4 + 2 + par] * invc[e];
                if (vj[e]) {
                    int ij = i * 64 + jc[e];
                    bool posA = hA && (iou[(size_t)sA * N2 + ij] > 0.5f);
                    bool posB = hB && (iou[(size_t)sB * N2 + ij] > 0.5f);
                    if (!posA) rA += __expf(scA * 10.f);
                    if (!posB) rB += __expf(scB * 10.f);
                    for (int cc = 0; cc < nc; cc++)
                        if (capC[cc] == jc[e]) {
                            g_all[capS4[cc] * SS + sA] = scA;
                            g_all[capS4[cc] * SS + sB] = scB;
                        }
                }
            }
            rsum[mt * 2] = rA;
            rsum[mt * 2 + 1] = rB;
        }
#pragma unroll
        for (int k = 0; k < 8; k++) {
            rsum[k] += __shfl_xor_sync(~0u, rsum[k], 1);
            rsum[k] += __shfl_xor_sync(~0u, rsum[k], 2);
        }
        if (q == 0) {
#pragma unroll
            for (int mt = 0; mt < 4; mt++) {
                atomicAdd(&sneg[mt * 16 + nl], rsum[mt * 2]);
                atomicAdd(&sneg[mt * 16 + nl + 8], rsum[mt * 2 + 1]);
            }
        }
    }
    __syncthreads();
    if (tid < SS) atomicAdd(&g_negsum[tid], sneg[tid]);

    // last-CTA final reduction
    __threadfence();
    __syncthreads();
    if (tid == 0) flag = (atomicAdd(&g_done, 1u) == (unsigned)(32 * BB - 1));
    __syncthreads();
    if (flag) {
        if (tid < SS) {
            int s = tid;
            float pos = __ldcg(&g_all[s * SS + s]);
            float sum = 0.f;
            for (int u = 0; u < SS; u++)
                if (u != s) sum += expf(__ldcg(&g_all[s * SS + u]) * 10.f);
            float pv = pos * 10.f;
            red[s] = -(pv - logf(expf(pv) + sum));
            red[64 + s] = -(pv - logf(expf(pv) + __ldcg(&g_negsum[s])));
        }
        __syncthreads();
        if (tid == 0) {
            float a = 0.f, bq = 0.f;
            for (int u = 0; u < SS; u++) { a += red[u]; bq += red[64 + u]; }
            out[0] = a / SS;
            out[1] = bq / SS;
        }
    }
}

// ---------------------------------------------------------------------------
extern "C" void kernel_launch(void* const* d_in, const int* in_sizes, int n_in,
                              void* d_out, int out_size) {
    const float* video = (const float*)d_in[0];
    const float* sents = (const float*)d_in[1];
    const int*   ntgt  = (const int*)d_in[2];
    const float* iou   = (const float*)d_in[3];
    float* out = (float*)d_out;

    cudaFuncSetAttribute(k_main, cudaFuncAttributeMaxDynamicSharedMemorySize, DSM_BYTES);
    cudaFuncSetAttribute(k_main, cudaFuncAttributePreferredSharedMemoryCarveout, 100);

    k_prep<<<65, 256>>>(sents, iou, ntgt);
    k_main<<<dim3(32, BB), 256, DSM_BYTES>>>(video, iou, out);
}

// round 17
// speedup vs baseline: 1.2137x; 1.2137x over previous
#include <cuda_runtime.h>
#include <cuda_fp16.h>
#include <cstdint>
#include <math.h>

#define BB 32
#define SS 64
#define CC 256
#define N2 4096

__device__ int      g_topk[SS];
__device__ int      g_vstart[BB + 1];
__device__ float    g_negsum[SS];
__device__ float    g_all[SS * SS];
__device__ uint4    g_Afr[16 * 4 * 32];   // A in MMA-fragment order [ks][mt][lane]
__device__ unsigned g_done;

#define MMAF16(d, a0, a1, a2, a3, b0, b1) \
    asm volatile("mma.sync.aligned.m16n8k16.row.col.f32.f16.f16.f32 " \
                 "{%0,%1,%2,%3}, {%4,%5,%6,%7}, {%8,%9}, {%0,%1,%2,%3};" \
                 : "+f"((d)[0]), "+f"((d)[1]), "+f"((d)[2]), "+f"((d)[3]) \
                 : "r"(a0), "r"(a1), "r"(a2), "r"(a3), "r"(b0), "r"(b1))

#define PF_L2(addr) asm volatile("prefetch.global.L2 [%0];" :: "l"(addr))

// ---------------------------------------------------------------------------
// k_prep: bid<64 = sentence s: normalize -> fragment-order A; iou argmax.
//         bid==64: vstart prefix + negsum + g_done init.
__global__ void k_prep(const float* __restrict__ sents, const float* __restrict__ iou,
                       const int* __restrict__ ntgt) {
    int bid = blockIdx.x, tid = threadIdx.x;
    if (bid == 64) {
        if (tid < SS) g_negsum[tid] = 0.f;
        if (tid == 0) {
            g_done = 0u;
            int acc = 0;
            g_vstart[0] = 0;
            for (int b = 0; b < BB; b++) {
                acc += ntgt[b];
                if (acc > SS) acc = SS;
                g_vstart[b + 1] = acc;
            }
        }
        return;
    }
    int s = bid;
    int lane = tid & 31, w = tid >> 5;
    __shared__ float wsum[8];
    __shared__ float amax[8];
    __shared__ int   aidx[8];

    float x = sents[s * CC + tid];
    float q = x * x;
#pragma unroll
    for (int o = 16; o; o >>= 1) q += __shfl_xor_sync(~0u, q, o);
    if (lane == 0) wsum[w] = q;
    __syncthreads();
    float tot = wsum[0] + wsum[1] + wsum[2] + wsum[3] +
                wsum[4] + wsum[5] + wsum[6] + wsum[7];
    float inv = 1.f / fmaxf(sqrtf(tot), 1e-12f);
    __half h = __float2half_rn(x * inv);
    int c = tid;
    // fragment-order byte offset: a0/a1/a2/a3 packed per lane as uint4
    int u4 = ((c >> 4) * 4 + (s >> 4)) * 32 + (s & 7) * 4 + ((c & 7) >> 1);
    int byte = u4 * 16 + ((s >> 3) & 1) * 4 + ((c >> 3) & 1) * 8 + (c & 1) * 2;
    *(__half*)((char*)g_Afr + byte) = h;

    float best = -1.f;
    int bi = 0;
    const float* irow = iou + (size_t)s * N2;
#pragma unroll
    for (int k = 0; k < 16; k++) {
        int ij = tid + 256 * k;
        if ((ij & 63) >= (ij >> 6)) {
            float v = irow[ij];
            if (v > best) { best = v; bi = ij; }
        }
    }
#pragma unroll
    for (int o = 16; o; o >>= 1) {
        float ov = __shfl_xor_sync(~0u, best, o);
        int   oi = __shfl_xor_sync(~0u, bi, o);
        if (ov > best || (ov == best && oi < bi)) { best = ov; bi = oi; }
    }
    if (lane == 0) { amax[w] = best; aidx[w] = bi; }
    __syncthreads();
    if (tid == 0) {
        float bb = amax[0]; int ii = aidx[0];
        for (int k = 1; k < 8; k++)
            if (amax[k] > bb || (amax[k] == bb && aidx[k] < ii)) { bb = amax[k]; ii = aidx[k]; }
        g_topk[s] = ii;
    }
}

// ---------------------------------------------------------------------------
// k_main: warp-autonomous (R9 structure) + L2 prefetch 4 iterations ahead.
// Each warp = one 16-prop strip x 64 sents x K=256. No mainloop barriers.
__global__ void __launch_bounds__(256, 3) k_main(const float* __restrict__ video,
                                                 const float* __restrict__ iou,
                                                 float* __restrict__ out) {
    __shared__ float sneg[SS];
    __shared__ float red[128];
    __shared__ int   flag;

    int tid = threadIdx.x;
    int lane = tid & 31, w = tid >> 5;
    int b = blockIdx.y;
    int sid = blockIdx.x * 8 + w;          // 0..159

    // strip -> (row i, 16-col block kq)
    int i, kq;
    if (sid < 64)       { i = sid >> 2;               kq = sid & 3; }
    else if (sid < 112) { int r = sid - 64;  i = 16 + r / 3;  kq = r % 3 + 1; }
    else if (sid < 144) { int r = sid - 112; i = 32 + (r >> 1); kq = (r & 1) + 2; }
    else                { i = 48 + (sid - 144);        kq = 3; }
    int j0 = kq * 16;
    int p0 = i * 64 + j0;

    if (tid < SS) sneg[tid] = 0.f;
    __syncthreads();

    int q = lane & 3, nl = lane >> 2;
    const float* Bs = video + (size_t)b * CC * N2 + p0;   // strip base (128B aligned)
    const float* B0 = Bs + nl;                             // prop p0+nl
    const float* B1 = B0 + 8;                              // prop p0+8+nl
    const uint4* Af = g_Afr + lane;

    // prologue prefetch: iterations 0..3 (each = 16 channel lines)
    {
        int pfi = (lane >> 4);            // 0 or 1
        const char* pa = (const char*)Bs;
        PF_L2(pa + (size_t)((pfi * 16) + (lane & 15)) * N2 * 4);
        PF_L2(pa + (size_t)(((pfi + 2) * 16) + (lane & 15)) * N2 * 4);
    }

    float acc[32];
#pragma unroll
    for (int k = 0; k < 32; k++) acc[k] = 0.f;
    float ss0 = 0.f, ss1 = 0.f;

#pragma unroll 4
    for (int ks = 0; ks < 16; ks++) {
        // L2 prefetch 4-5 iterations ahead (one instr per 2 iters)
        if ((ks & 1) == 0) {
            int pfi = ks + 4 + (lane >> 4);
            if (pfi < 16)
                PF_L2((const char*)Bs + (size_t)(pfi * 16 + (lane & 15)) * N2 * 4);
        }
        size_t kb = (size_t)(ks * 16 + 2 * q) * N2;
        const float* c0 = B0 + kb;
        const float* c1 = B1 + kb;
        float x0 = __ldg(c0);
        float x1 = __ldg(c0 + N2);
        float x2 = __ldg(c0 + 8 * N2);
        float x3 = __ldg(c0 + 9 * N2);
        float y0 = __ldg(c1);
        float y1 = __ldg(c1 + N2);
        float y2 = __ldg(c1 + 8 * N2);
        float y3 = __ldg(c1 + 9 * N2);
        ss0 += x0 * x0 + x1 * x1 + x2 * x2 + x3 * x3;
        ss1 += y0 * y0 + y1 * y1 + y2 * y2 + y3 * y3;
        __half2 p00 = __floats2half2_rn(x0, x1);
        __half2 p01 = __floats2half2_rn(x2, x3);
        __half2 p10 = __floats2half2_rn(y0, y1);
        __half2 p11 = __floats2half2_rn(y2, y3);
        uint32_t b00 = *(uint32_t*)&p00, b01 = *(uint32_t*)&p01;
        uint32_t b10 = *(uint32_t*)&p10, b11 = *(uint32_t*)&p11;
#pragma unroll
        for (int mt = 0; mt < 4; mt++) {
            uint4 a = Af[(ks * 4 + mt) * 32];
            MMAF16(acc + mt * 8,     a.x, a.y, a.z, a.w, b00, b01);
            MMAF16(acc + mt * 8 + 4, a.x, a.y, a.z, a.w, b10, b11);
        }
    }

    // per-prop inverse norms: quad holds prop (nl) channels
    ss0 += __shfl_xor_sync(~0u, ss0, 1); ss0 += __shfl_xor_sync(~0u, ss0, 2);
    ss1 += __shfl_xor_sync(~0u, ss1, 1); ss1 += __shfl_xor_sync(~0u, ss1, 2);
    float inv0 = rsqrtf(fmaxf(ss0, 1e-24f));   // prop p0+nl
    float inv1 = rsqrtf(fmaxf(ss1, 1e-24f));   // prop p0+8+nl
    float invc[4];
    invc[0] = __shfl_sync(~0u, inv0, 8 * q);
    invc[1] = __shfl_sync(~0u, inv0, 8 * q + 4);
    invc[2] = __shfl_sync(~0u, inv1, 8 * q);
    invc[3] = __shfl_sync(~0u, inv1, 8 * q + 4);

    int jc[4];
    jc[0] = j0 + 2 * q;     jc[1] = jc[0] + 1;
    jc[2] = j0 + 8 + 2 * q; jc[3] = jc[2] + 1;
    bool vj[4];
#pragma unroll
    for (int e = 0; e < 4; e++) vj[e] = (jc[e] >= i);

    int vs0 = g_vstart[b], vs1 = g_vstart[b + 1];
    // capture list: home sentences whose topk prop is in this strip
    int nc = 0, capC[4], capS4[4];
    for (int cs = vs0; cs < vs1; cs++) {
        int rel = g_topk[cs] - i * 64 - j0;
        if (rel >= 0 && rel < 16 && nc < 4) { capC[nc] = j0 + rel; capS4[nc] = cs; nc++; }
    }

    float rsum[8];
#pragma unroll
    for (int mt = 0; mt < 4; mt++) {
        int sA = mt * 16 + nl, sB = sA + 8;
        bool hA = (sA >= vs0 && sA < vs1);
        bool hB = (sB >= vs0 && sB < vs1);
        float rA = 0.f, rB = 0.f;
#pragma unroll
        for (int e = 0; e < 4; e++) {
            int blk = e >> 1, par = e & 1;
            float scA = acc[mt * 8 + blk * 4 + par] * invc[e];
            float scB = acc[mt * 8 + blk * 4 + 2 + par] * invc[e];
            if (vj[e]) {
                int ij = i * 64 + jc[e];
                bool posA = hA && (iou[(size_t)sA * N2 + ij] > 0.5f);
                bool posB = hB && (iou[(size_t)sB * N2 + ij] > 0.5f);
                if (!posA) rA += __expf(scA * 10.f);
                if (!posB) rB += __expf(scB * 10.f);
                for (int cc = 0; cc < nc; cc++)
                    if (capC[cc] == jc[e]) {
                        g_all[capS4[cc] * SS + sA] = scA;
                        g_all[capS4[cc] * SS + sB] = scB;
                    }
            }
        }
        rsum[mt * 2] = rA;
        rsum[mt * 2 + 1] = rB;
    }
    // reduce over quad (same rows, different cols), then smem
#pragma unroll
    for (int k = 0; k < 8; k++) {
        rsum[k] += __shfl_xor_sync(~0u, rsum[k], 1);
        rsum[k] += __shfl_xor_sync(~0u, rsum[k], 2);
    }
    if (q == 0) {
#pragma unroll
        for (int mt = 0; mt < 4; mt++) {
            atomicAdd(&sneg[mt * 16 + nl], rsum[mt * 2]);
            atomicAdd(&sneg[mt * 16 + nl + 8], rsum[mt * 2 + 1]);
        }
    }
    __syncthreads();
    if (tid < SS) atomicAdd(&g_negsum[tid], sneg[tid]);

    // last-CTA final reduction
    __threadfence();
    __syncthreads();
    if (tid == 0) flag = (atomicAdd(&g_done, 1u) == (unsigned)(20 * BB - 1));
    __syncthreads();
    if (flag) {
        if (tid < SS) {
            int s = tid;
            float pos = __ldcg(&g_all[s * SS + s]);
            float sum = 0.f;
            for (int u = 0; u < SS; u++)
                if (u != s) sum += expf(__ldcg(&g_all[s * SS + u]) * 10.f);
            float pv = pos * 10.f;
            red[s] = -(pv - logf(expf(pv) + sum));
            red[64 + s] = -(pv - logf(expf(pv) + __ldcg(&g_negsum[s])));
        }
        __syncthreads();
        if (tid == 0) {
            float a = 0.f, bq = 0.f;
            for (int u = 0; u < SS; u++) { a += red[u]; bq += red[64 + u]; }
            out[0] = a / SS;
            out[1] = bq / SS;
        }
    }
}

// ---------------------------------------------------------------------------
extern "C" void kernel_launch(void* const* d_in, const int* in_sizes, int n_in,
                              void* d_out, int out_size) {
    const float* video = (const float*)d_in[0];
    const float* sents = (const float*)d_in[1];
    const int*   ntgt  = (const int*)d_in[2];
    const float* iou   = (const float*)d_in[3];
    float* out = (float*)d_out;

    k_prep<<<65, 256>>>(sents, iou, ntgt);
    k_main<<<dim3(20, BB), 256>>>(video, iou, out);
}